// round 10
// baseline (speedup 1.0000x reference)
#include <cuda_runtime.h>
#include <cuda_bf16.h>

// Problem dims (fixed by reference)
#define BB   16
#define TT   256
#define KK   128
#define DE   256
#define DK   256
#define UU   128

#define TILE_T 7
#define TPB    37                 // tiles per batch: 36*7 + 4 = 256
#define GRID_ATTN (BB * TPB)      // 592 = 4 * 148 -> one perfectly balanced wave

#define CHUNK_U 32
#define NCHUNK  (UU / CHUNK_U)    // 4
#define KROW    33                // padded smem row (odd -> conflict-free LDS)

// Scratch (allocation-free rule -> __device__ globals; zero-initialized)
__device__ __align__(16) float g_E [BB * TT * UU + 8 * UU]; // padded for ragged tail
__device__ __align__(16) float g_Kp[BB * KK * UU];          // [B, K, U]  (R2 layout)

typedef unsigned long long u64;

__device__ __forceinline__ float fast_tanh(float x) {
    float y; asm("tanh.approx.f32 %0, %1;" : "=f"(y) : "f"(x)); return y;
}
__device__ __forceinline__ u64 pack2(float lo, float hi) {
    u64 r; asm("mov.b64 %0, {%1, %2};" : "=l"(r) : "f"(lo), "f"(hi)); return r;
}
__device__ __forceinline__ void unpack2(u64 v, float& lo, float& hi) {
    asm("mov.b64 {%0, %1}, %2;" : "=f"(lo), "=f"(hi) : "l"(v));
}
__device__ __forceinline__ u64 fma2(u64 a, u64 b, u64 c) {   // packed f32x2 fma
    u64 d; asm("fma.rn.f32x2 %0, %1, %2, %3;" : "=l"(d) : "l"(a), "l"(b), "l"(c)); return d;
}
__device__ __forceinline__ unsigned smem_u32(const void* p) {
    unsigned a;
    asm("{ .reg .u64 t; cvta.to.shared.u64 t, %1; cvt.u32.u64 %0, t; }" : "=r"(a) : "l"(p));
    return a;
}
__device__ __forceinline__ void cp_async4(unsigned saddr, const void* gptr) {
    asm volatile("cp.async.ca.shared.global [%0], [%1], 4;" :: "r"(saddr), "l"(gptr));
}

// ---------------------------------------------------------------------------
// Prologue (exact R2 structure, ~3.7us): 4 rows per CTA, 128 threads.
// Blocks [0,1024)   -> E rows   (coalesced writes)
// Blocks [1024,1536)-> Kp rows  (coalesced writes, straight [B,K,U] layout)
// ---------------------------------------------------------------------------
__global__ void __launch_bounds__(128) prep_kernel(
    const float* __restrict__ enc, const float* __restrict__ kn,
    const float* __restrict__ W1,  const float* __restrict__ b1,
    const float* __restrict__ W2,  const float* __restrict__ b2)
{
    const bool isE = (blockIdx.x < 1024);
    const int  rbase = (isE ? blockIdx.x : (blockIdx.x - 1024)) * 4;
    const float* __restrict__ X    = isE ? enc : kn;
    const float* __restrict__ W    = isE ? W1  : W2;
    const float* __restrict__ bias = isE ? b1  : b2;
    float* __restrict__ O = isE ? g_E : g_Kp;

    __shared__ float sX[4][DE];
    const int tid = threadIdx.x;  // also the output u index
    #pragma unroll
    for (int r = 0; r < 4; r++) {
        sX[r][tid]       = X[(rbase + r) * DE + tid];
        sX[r][tid + 128] = X[(rbase + r) * DE + tid + 128];
    }
    __syncthreads();

    float a0 = 0.f, a1 = 0.f, a2 = 0.f, a3 = 0.f;
    #pragma unroll 8
    for (int d = 0; d < DE; d++) {
        const float w = W[d * UU + tid];       // coalesced; L1-hot
        a0 = fmaf(sX[0][d], w, a0);
        a1 = fmaf(sX[1][d], w, a1);
        a2 = fmaf(sX[2][d], w, a2);
        a3 = fmaf(sX[3][d], w, a3);
    }
    const float bb = bias[tid];
    O[(rbase + 0) * UU + tid] = a0 + bb;
    O[(rbase + 1) * UU + tid] = a1 + bb;
    O[(rbase + 2) * UU + tid] = a2 + bb;
    O[(rbase + 3) * UU + tid] = a3 + bb;
}

// ---------------------------------------------------------------------------
// Main kernel: one CTA per (b, 7-row t-tile). 256 threads, 4 CTAs/SM, 1 wave.
// smem: sKp double-buffer 2 x [128 k][33] 33.8KB | sE[u][8] 4KB (col7=V) | sA/sB 8KB
//  stage:   4B cp.async gathers chunk [128 k][32 u] from k-major g_Kp,
//           transposing into padded k-rows (odd stride -> conflict-free reads).
//  phase 1: thread (k = tid&127, uh = tid>>7): 16 u per chunk from its half;
//           inner loop = pure LDS + tanh math. 8 barriers total.
//  phase 2: warp w (<7): softmax row t=w, summing the two u-half partials.
//  phase 3: thread = d: context via packed f32x2 FMA, LDS.64 attn pairs.
// ---------------------------------------------------------------------------
__global__ void __launch_bounds__(256, 4) attn_kernel(
    const float* __restrict__ kn, const float* __restrict__ V,
    float* __restrict__ out)
{
    __shared__ __align__(16) float sKp[2][KK * KROW];   // 2 x 16.9KB
    __shared__ __align__(16) float sE[UU][8];   // [u][t0..t6, V]
    __shared__ __align__(16) float sA[KK][8];   // u-half 0 partials -> attn
    __shared__ __align__(16) float sB[KK][8];   // u-half 1 partials

    const int tile = blockIdx.x;
    const int b    = tile / TPB;
    const int t0   = (tile - b * TPB) * TILE_T;
    const int nt   = min(TILE_T, TT - t0);       // 7, or 4 on the tail tile
    const int tid  = threadIdx.x;

    const float* __restrict__ kpBase = g_Kp + b * KK * UU;
    const unsigned sKpAddr[2] = { smem_u32(&sKp[0][0]), smem_u32(&sKp[1][0]) };

    // cp.async mapping: thread t covers k-rows (t>>3) + 32*j, u = (t&7)*4 + i
    const int cpk = tid >> 3;          // base k row (0..31)
    const int cpu = (tid & 7) * 4;     // u offset within chunk (0,4,..,28)

    // stage chunk 0 (+ E tile with V in col 7) before first barrier
    {
        #pragma unroll
        for (int j = 0; j < 4; j++) {
            const int kr = cpk + 32 * j;
            const float* g = kpBase + kr * UU + cpu;        // chunk 0: u0 = 0
            const unsigned s = sKpAddr[0] + (kr * KROW + cpu) * 4;
            #pragma unroll
            for (int i = 0; i < 4; i++) cp_async4(s + i * 4, g + i);
        }
        asm volatile("cp.async.commit_group;");
    }
    if (tid < UU) {
        float ev[8];
        #pragma unroll
        for (int i = 0; i < 7; i++)
            ev[i] = g_E[(b * TT + t0 + i) * UU + tid];
        ev[7] = V[tid];                          // V packed into col 7
        float4* dst = (float4*)&sE[tid][0];
        dst[0] = make_float4(ev[0], ev[1], ev[2], ev[3]);
        dst[1] = make_float4(ev[4], ev[5], ev[6], ev[7]);
    }

    // ---- phase 1: scores, double-buffered Kp chunks ----
    const int k  = tid & (KK - 1);
    const int uh = tid >> 7;                     // 0/1: first/last 16 u of chunk
    float acc[7];
    #pragma unroll
    for (int i = 0; i < 7; i++) acc[i] = 0.f;

    #pragma unroll
    for (int c = 0; c < NCHUNK; c++) {
        if (c + 1 < NCHUNK) {                    // prefetch next chunk
            const unsigned sdst = sKpAddr[(c + 1) & 1];
            const int u0 = (c + 1) * CHUNK_U;
            #pragma unroll
            for (int j = 0; j < 4; j++) {
                const int kr = cpk + 32 * j;
                const float* g = kpBase + kr * UU + u0 + cpu;
                const unsigned s = sdst + (kr * KROW + cpu) * 4;
                #pragma unroll
                for (int i = 0; i < 4; i++) cp_async4(s + i * 4, g + i);
            }
            asm volatile("cp.async.commit_group;");
            asm volatile("cp.async.wait_group 1;");
        } else {
            asm volatile("cp.async.wait_group 0;");
        }
        __syncthreads();

        const float* __restrict__ kp = &sKp[c & 1][k * KROW + uh * 16];
        const float* __restrict__ eR = &sE[c * CHUNK_U + uh * 16][0];
        #pragma unroll
        for (int j = 0; j < 16; j++) {
            const float kpv  = kp[j];                         // conflict-free LDS
            const float4 e03 = *(const float4*)(eR + j * 8);      // broadcast
            const float4 e47 = *(const float4*)(eR + j * 8 + 4);  // broadcast
            const float vv   = e47.w;                             // V[u]
            acc[0] = fmaf(fast_tanh(e03.x + kpv), vv, acc[0]);
            acc[1] = fmaf(fast_tanh(e03.y + kpv), vv, acc[1]);
            acc[2] = fmaf(fast_tanh(e03.z + kpv), vv, acc[2]);
            acc[3] = fmaf(fast_tanh(e03.w + kpv), vv, acc[3]);
            acc[4] = fmaf(fast_tanh(e47.x + kpv), vv, acc[4]);
            acc[5] = fmaf(fast_tanh(e47.y + kpv), vv, acc[5]);
            acc[6] = fmaf(fast_tanh(e47.z + kpv), vv, acc[6]);
        }
        __syncthreads();                         // buffer reuse fence
    }
    {
        float4* dst = (float4*)(uh ? &sB[k][0] : &sA[k][0]);
        dst[0] = make_float4(acc[0], acc[1], acc[2], acc[3]);
        dst[1] = make_float4(acc[4], acc[5], acc[6], 0.f);   // col 7 pad = 0
    }
    __syncthreads();

    // ---- phase 2: softmax over K (warp w handles row t = w) ----
    {
        const int w = tid >> 5, lane = tid & 31;
        if (w < 7) {
            float s0 = sA[lane      ][w] + sB[lane      ][w];
            float s1 = sA[lane + 32 ][w] + sB[lane + 32 ][w];
            float s2 = sA[lane + 64 ][w] + sB[lane + 64 ][w];
            float s3 = sA[lane + 96 ][w] + sB[lane + 96 ][w];
            float m = fmaxf(fmaxf(s0, s1), fmaxf(s2, s3));
            #pragma unroll
            for (int off = 16; off; off >>= 1)
                m = fmaxf(m, __shfl_xor_sync(0xffffffffu, m, off));
            const float p0 = __expf(s0 - m), p1 = __expf(s1 - m);
            const float p2 = __expf(s2 - m), p3 = __expf(s3 - m);
            float sum = (p0 + p1) + (p2 + p3);
            #pragma unroll
            for (int off = 16; off; off >>= 1)
                sum += __shfl_xor_sync(0xffffffffu, sum, off);
            const float inv = 1.0f / sum;
            sA[lane      ][w] = p0 * inv;        // attn overwrites sA; col 7 stays 0
            sA[lane + 32 ][w] = p1 * inv;
            sA[lane + 64 ][w] = p2 * inv;
            sA[lane + 96 ][w] = p3 * inv;
        }
    }
    __syncthreads();

    // ---- phase 3: context, thread = d, packed f32x2 over t-pairs ----
    {
        const float* __restrict__ knP = kn + b * KK * DK + tid;
        u64 a01 = 0, a23 = 0, a45 = 0, a6x = 0;
        #pragma unroll 8
        for (int kk = 0; kk < KK; kk++) {
            const float kv = __ldg(knP + kk * DK);        // coalesced, L2-hot
            const u64   kd = pack2(kv, kv);
            const u64* __restrict__ at = (const u64*)&sA[kk][0];  // broadcast LDS.64
            a01 = fma2(at[0], kd, a01);
            a23 = fma2(at[1], kd, a23);
            a45 = fma2(at[2], kd, a45);
            a6x = fma2(at[3], kd, a6x);                   // hi lane = pad (0)
        }
        float c[8];
        unpack2(a01, c[0], c[1]); unpack2(a23, c[2], c[3]);
        unpack2(a45, c[4], c[5]); unpack2(a6x, c[6], c[7]);

        float* __restrict__ oB = out + (b * TT + t0) * DK + tid;
        #pragma unroll
        for (int i = 0; i < 7; i++)
            if (i < nt) oB[i * DK] = c[i];
    }
}

extern "C" void kernel_launch(void* const* d_in, const int* in_sizes, int n_in,
                              void* d_out, int out_size)
{
    // metadata order: knowledge_onehot, encoder_outputs, W1, b1, W2, b2, V, bV
    const float* kn  = (const float*)d_in[0];
    const float* enc = (const float*)d_in[1];
    const float* W1  = (const float*)d_in[2];
    const float* b1  = (const float*)d_in[3];
    const float* W2  = (const float*)d_in[4];
    const float* b2  = (const float*)d_in[5];
    const float* V   = (const float*)d_in[6];
    float* out = (float*)d_out;

    prep_kernel<<<1536, 128>>>(enc, kn, W1, b1, W2, b2);
    attn_kernel<<<GRID_ATTN, 256>>>(kn, V, out);
}

// round 12
// speedup vs baseline: 1.0856x; 1.0856x over previous
#include <cuda_runtime.h>
#include <cuda_bf16.h>
#include <cuda_fp16.h>

// Problem dims (fixed by reference)
#define BB   16
#define TT   256
#define KK   128
#define DE   256
#define DK   256
#define UU   128

#define TILE_T 7
#define TPB    37                 // tiles per batch: 36*7 + 4 = 256
#define GRID_ATTN (BB * TPB)      // 592 = 4 * 148 -> one perfectly balanced wave

#define CHUNK_U 16
#define NCHUNK  (UU / CHUNK_U)    // 8

// Scratch (allocation-free rule -> __device__ globals; zero-initialized)
__device__ __align__(16) float g_E  [BB * TT * UU + 8 * UU]; // padded for ragged tail
__device__ __align__(16) float g_KpT[BB * UU * KK];          // [B, U, K]

typedef unsigned long long u64;
typedef unsigned int u32;

__device__ __forceinline__ u64 pack2(float lo, float hi) {
    u64 r; asm("mov.b64 %0, {%1, %2};" : "=l"(r) : "f"(lo), "f"(hi)); return r;
}
__device__ __forceinline__ void unpack2(u64 v, float& lo, float& hi) {
    asm("mov.b64 {%0, %1}, %2;" : "=f"(lo), "=f"(hi) : "l"(v));
}
__device__ __forceinline__ u64 fma2(u64 a, u64 b, u64 c) {   // packed f32x2 fma
    u64 d; asm("fma.rn.f32x2 %0, %1, %2, %3;" : "=l"(d) : "l"(a), "l"(b), "l"(c)); return d;
}
__device__ __forceinline__ u32 hadd2u(u32 a, u32 b) {
    u32 d; asm("add.f16x2 %0, %1, %2;" : "=r"(d) : "r"(a), "r"(b)); return d;
}
__device__ __forceinline__ u32 tanh2u(u32 x) {
    u32 d; asm("tanh.approx.f16x2 %0, %1;" : "=r"(d) : "r"(x)); return d;
}
__device__ __forceinline__ float2 h2_to_f2(u32 h) {
    __half2 hh = *reinterpret_cast<__half2*>(&h);
    return __half22float2(hh);
}
__device__ __forceinline__ u32 f2_to_h2(float lo, float hi) {
    __half2 hh = __floats2half2_rn(lo, hi);     // .x = lo, .y = hi
    return *reinterpret_cast<u32*>(&hh);
}
__device__ __forceinline__ unsigned smem_u32(const void* p) {
    unsigned a;
    asm("{ .reg .u64 t; cvta.to.shared.u64 t, %1; cvt.u32.u64 %0, t; }" : "=r"(a) : "l"(p));
    return a;
}
__device__ __forceinline__ void cp_async16(unsigned saddr, const void* gptr) {
    asm volatile("cp.async.cg.shared.global [%0], [%1], 16;" :: "r"(saddr), "l"(gptr));
}

// ---------------------------------------------------------------------------
// Prologue (R5 f32x2 version): 8 rows per CTA, 128 threads (thread = u).
// Packed fma.rn.f32x2 -> FFMA2 halves the FFMA-pipe floor.
// Blocks [0,512)  -> E rows  (4096 rows of enc[4096,256] @ W1[256,128])
// Blocks [512,768)-> Kp rows, written TRANSPOSED per batch: g_KpT[b][u][k]
// ---------------------------------------------------------------------------
__global__ void __launch_bounds__(128) prep_kernel(
    const float* __restrict__ enc, const float* __restrict__ kn,
    const float* __restrict__ W1,  const float* __restrict__ b1,
    const float* __restrict__ W2,  const float* __restrict__ b2)
{
    const bool isE   = (blockIdx.x < 512);
    const int  rbase = (isE ? blockIdx.x : (blockIdx.x - 512)) * 8;
    const float* __restrict__ X    = isE ? enc : kn;
    const float* __restrict__ W    = isE ? W1  : W2;
    const float* __restrict__ bias = isE ? b1  : b2;

    // sX[d][r], r = 0..7, padded to 10 floats/row (b64-aligned rows)
    __shared__ float sX[DE][10];
    const int tid = threadIdx.x;                 // also the output u index
    #pragma unroll
    for (int r = 0; r < 8; r++) {
        sX[tid      ][r] = X[(rbase + r) * DE + tid];
        sX[tid + 128][r] = X[(rbase + r) * DE + tid + 128];
    }
    __syncthreads();

    u64 a01 = 0, a23 = 0, a45 = 0, a67 = 0;      // bit-zero == (0.0f, 0.0f)
    #pragma unroll 4
    for (int d = 0; d < DE; d++) {
        const float w  = W[d * UU + tid];        // coalesced; L1-hot
        const u64   wd = pack2(w, w);
        const u64* __restrict__ xr = (const u64*)&sX[d][0];   // broadcast LDS.64 x4
        a01 = fma2(xr[0], wd, a01);
        a23 = fma2(xr[1], wd, a23);
        a45 = fma2(xr[2], wd, a45);
        a67 = fma2(xr[3], wd, a67);
    }
    float a[8];
    unpack2(a01, a[0], a[1]); unpack2(a23, a[2], a[3]);
    unpack2(a45, a[4], a[5]); unpack2(a67, a[6], a[7]);
    const float bb = bias[tid];

    if (isE) {
        #pragma unroll
        for (int r = 0; r < 8; r++)
            g_E[(rbase + r) * UU + tid] = a[r] + bb;
    } else {
        #pragma unroll
        for (int r = 0; r < 8; r++) {
            const int row = rbase + r;           // global knowledge row = b*K + k
            const int b = row >> 7;
            const int k = row & (KK - 1);
            g_KpT[(b * UU + tid) * KK + k] = a[r] + bb;
        }
    }
}

// ---------------------------------------------------------------------------
// Main kernel: one CTA per (b, 7-row t-tile). 256 threads, 4 CTAs/SM, 1 wave.
// smem: sKp double-buffer 16KB | sE16[u] 2KB (4 f16x2 t-pairs) | sV 0.5KB | sA/sB 8KB
//  phase 1: Kp staged via 16B cp.async chunks from u-major g_KpT;
//           tanh.approx.f16x2 on t-pairs, fp32 accumulation.
//  phase 2: warp w (<7): softmax row t=w, summing the two u-half partials.
//  phase 3: thread = d: context via packed f32x2 FMA over t-pairs.
// ---------------------------------------------------------------------------
__global__ void __launch_bounds__(256, 4) attn_kernel(
    const float* __restrict__ kn, const float* __restrict__ V,
    float* __restrict__ out)
{
    __shared__ __align__(16) float sKp[2][CHUNK_U * KK];  // 2 x 8KB
    __shared__ __align__(16) uint4 sE16[UU];    // per u: 4 f16x2 pairs {t01,t23,t45,t6+pad}
    __shared__ __align__(16) float sV[UU];
    __shared__ __align__(16) float sA[KK][8];   // u-half 0 partials -> attn
    __shared__ __align__(16) float sB[KK][8];   // u-half 1 partials

    const int tile = blockIdx.x;
    const int b    = tile / TPB;
    const int t0   = (tile - b * TPB) * TILE_T;
    const int nt   = min(TILE_T, TT - t0);       // 7, or 4 on the tail tile
    const int tid  = threadIdx.x;

    const float* __restrict__ kpBase = g_KpT + b * UU * KK;
    const unsigned sKp0 = smem_u32(&sKp[0][0]);
    const unsigned sKp1 = smem_u32(&sKp[1][0]);

    // stage chunk 0 (16 u x 128 k, contiguous 8KB) before first barrier
    {
        const char* g = (const char*)kpBase + tid * 32;
        cp_async16(sKp0 + tid * 32,      g);
        cp_async16(sKp0 + tid * 32 + 16, g + 16);
        asm volatile("cp.async.commit_group;");
    }
    // stage E tile as f16x2 t-pairs + V (fp32)
    if (tid < UU) {
        float ev[7];
        #pragma unroll
        for (int i = 0; i < 7; i++)
            ev[i] = g_E[(b * TT + t0 + i) * UU + tid];   // padded g_E: OOB-safe
        uint4 p;
        p.x = f2_to_h2(ev[0], ev[1]);
        p.y = f2_to_h2(ev[2], ev[3]);
        p.z = f2_to_h2(ev[4], ev[5]);
        p.w = f2_to_h2(ev[6], 0.0f);
        sE16[tid] = p;
        sV[tid] = V[tid];
    }

    // ---- phase 1: scores, double-buffered Kp chunks, f16x2 tanh ----
    const int k  = tid & (KK - 1);
    const int uh = tid >> 7;                     // 0/1: first/last 8 u of chunk
    float acc[7];
    #pragma unroll
    for (int i = 0; i < 7; i++) acc[i] = 0.f;

    #pragma unroll
    for (int c = 0; c < NCHUNK; c++) {
        if (c + 1 < NCHUNK) {                    // prefetch next chunk
            const unsigned sdst = ((c + 1) & 1) ? sKp1 : sKp0;
            const char* g = (const char*)(kpBase + (c + 1) * CHUNK_U * KK) + tid * 32;
            cp_async16(sdst + tid * 32,      g);
            cp_async16(sdst + tid * 32 + 16, g + 16);
            asm volatile("cp.async.commit_group;");
            asm volatile("cp.async.wait_group 1;");
        } else {
            asm volatile("cp.async.wait_group 0;");
        }
        __syncthreads();

        const float* __restrict__ kp = &sKp[c & 1][uh * 8 * KK + k];
        const uint4* __restrict__ eB = &sE16[c * CHUNK_U + uh * 8];
        const float* __restrict__ vB = &sV[c * CHUNK_U + uh * 8];
        #pragma unroll
        for (int j = 0; j < 8; j++) {
            const float kpv = kp[j * KK];                 // conflict-free LDS
            const u32   kp2 = f2_to_h2(kpv, kpv);         // 1 cvt
            const uint4 e4  = eB[j];                      // broadcast LDS.128
            const float vv  = vB[j];                      // broadcast LDS

            const float2 r0 = h2_to_f2(tanh2u(hadd2u(e4.x, kp2)));  // t0,t1
            const float2 r1 = h2_to_f2(tanh2u(hadd2u(e4.y, kp2)));  // t2,t3
            const float2 r2 = h2_to_f2(tanh2u(hadd2u(e4.z, kp2)));  // t4,t5
            const float2 r3 = h2_to_f2(tanh2u(hadd2u(e4.w, kp2)));  // t6,pad

            acc[0] = fmaf(r0.x, vv, acc[0]);
            acc[1] = fmaf(r0.y, vv, acc[1]);
            acc[2] = fmaf(r1.x, vv, acc[2]);
            acc[3] = fmaf(r1.y, vv, acc[3]);
            acc[4] = fmaf(r2.x, vv, acc[4]);
            acc[5] = fmaf(r2.y, vv, acc[5]);
            acc[6] = fmaf(r3.x, vv, acc[6]);
        }
        __syncthreads();                         // buffer reuse fence
    }
    {
        float4* dst = (float4*)(uh ? &sB[k][0] : &sA[k][0]);
        dst[0] = make_float4(acc[0], acc[1], acc[2], acc[3]);
        dst[1] = make_float4(acc[4], acc[5], acc[6], 0.f);   // col 7 pad = 0
    }
    __syncthreads();

    // ---- phase 2: softmax over K (warp w handles row t = w) ----
    {
        const int w = tid >> 5, lane = tid & 31;
        if (w < 7) {
            float s0 = sA[lane      ][w] + sB[lane      ][w];
            float s1 = sA[lane + 32 ][w] + sB[lane + 32 ][w];
            float s2 = sA[lane + 64 ][w] + sB[lane + 64 ][w];
            float s3 = sA[lane + 96 ][w] + sB[lane + 96 ][w];
            float m = fmaxf(fmaxf(s0, s1), fmaxf(s2, s3));
            #pragma unroll
            for (int off = 16; off; off >>= 1)
                m = fmaxf(m, __shfl_xor_sync(0xffffffffu, m, off));
            const float p0 = __expf(s0 - m), p1 = __expf(s1 - m);
            const float p2 = __expf(s2 - m), p3 = __expf(s3 - m);
            float sum = (p0 + p1) + (p2 + p3);
            #pragma unroll
            for (int off = 16; off; off >>= 1)
                sum += __shfl_xor_sync(0xffffffffu, sum, off);
            const float inv = 1.0f / sum;
            sA[lane      ][w] = p0 * inv;        // attn overwrites sA; col 7 stays 0
            sA[lane + 32 ][w] = p1 * inv;
            sA[lane + 64 ][w] = p2 * inv;
            sA[lane + 96 ][w] = p3 * inv;
        }
    }
    __syncthreads();

    // ---- phase 3: context, thread = d, packed f32x2 over t-pairs ----
    {
        const float* __restrict__ knP = kn + b * KK * DK + tid;
        u64 a01 = 0, a23 = 0, a45 = 0, a6x = 0;
        #pragma unroll 8
        for (int kk = 0; kk < KK; kk++) {
            const float kv = __ldg(knP + kk * DK);        // coalesced, L2-hot
            const u64   kd = pack2(kv, kv);
            const u64* __restrict__ at = (const u64*)&sA[kk][0];  // broadcast LDS.64
            a01 = fma2(at[0], kd, a01);
            a23 = fma2(at[1], kd, a23);
            a45 = fma2(at[2], kd, a45);
            a6x = fma2(at[3], kd, a6x);                   // hi lane = pad (0)
        }
        float c[8];
        unpack2(a01, c[0], c[1]); unpack2(a23, c[2], c[3]);
        unpack2(a45, c[4], c[5]); unpack2(a6x, c[6], c[7]);

        float* __restrict__ oB = out + (b * TT + t0) * DK + tid;
        #pragma unroll
        for (int i = 0; i < 7; i++)
            if (i < nt) oB[i * DK] = c[i];
    }
}

extern "C" void kernel_launch(void* const* d_in, const int* in_sizes, int n_in,
                              void* d_out, int out_size)
{
    // metadata order: knowledge_onehot, encoder_outputs, W1, b1, W2, b2, V, bV
    const float* kn  = (const float*)d_in[0];
    const float* enc = (const float*)d_in[1];
    const float* W1  = (const float*)d_in[2];
    const float* b1  = (const float*)d_in[3];
    const float* W2  = (const float*)d_in[4];
    const float* b2  = (const float*)d_in[5];
    const float* V   = (const float*)d_in[6];
    float* out = (float*)d_out;

    prep_kernel<<<768, 128>>>(enc, kn, W1, b1, W2, b2);
    attn_kernel<<<GRID_ATTN, 256>>>(kn, V, out);
}